// round 11
// baseline (speedup 1.0000x reference)
#include <cuda_runtime.h>
#include <cuda_fp16.h>
#include <math.h>
#include <stdint.h>

// Problem constants
#define NB 16
#define NT 2048
#define NC 384
#define NE 8
#define NDFF 1536
#define NTOK (NB*NT)          // 32768
#define CAP 8192
#define CHUNK 128
#define NCHUNK (NTOK/CHUNK)   // 256

// ---------------- device scratch ----------------
__device__ int   g_expert[NTOK];
__device__ float g_gate[NTOK];
__device__ int   g_hist[NCHUNK][NE];
__device__ int   g_base[NCHUNK][NE];
__device__ int   g_total[NE];
__device__ int   g_idx[NE*CAP];
__device__ float g_gslot[NE*CAP];

__device__ __half g_xh[(size_t)NTOK*NC];
__device__ __half g_w1h[(size_t)NE*NDFF*NC];   // [E][DFF][C] K-major
__device__ __half g_w2h[(size_t)NE*NC*NDFF];   // [E][C][DFF] K-major
__device__ __half g_Hh[(size_t)NE*CAP*NDFF];

// ---------------- helpers ----------------
__device__ __forceinline__ uint32_t smem_to_u32(const void* p) {
    uint32_t a;
    asm("{ .reg .u64 t; cvta.to.shared.u64 t, %1; cvt.u32.u64 %0, t; }" : "=r"(a) : "l"(p));
    return a;
}
__device__ __forceinline__ void ldsm4(uint32_t* r, uint32_t addr) {
    asm volatile("ldmatrix.sync.aligned.m8n8.x4.shared.b16 {%0,%1,%2,%3}, [%4];"
        : "=r"(r[0]), "=r"(r[1]), "=r"(r[2]), "=r"(r[3]) : "r"(addr));
}
__device__ __forceinline__ void mma16816(float* d, const uint32_t* a, const uint32_t* b) {
    asm volatile("mma.sync.aligned.m16n8k16.row.col.f32.f16.f16.f32 "
        "{%0,%1,%2,%3}, {%4,%5,%6,%7}, {%8,%9}, {%0,%1,%2,%3};"
        : "+f"(d[0]), "+f"(d[1]), "+f"(d[2]), "+f"(d[3])
        : "r"(a[0]), "r"(a[1]), "r"(a[2]), "r"(a[3]), "r"(b[0]), "r"(b[1]));
}
__device__ __forceinline__ void cp16(uint32_t dst, const void* src, int sz) {
    asm volatile("cp.async.cg.shared.global [%0], [%1], 16, %2;"
        :: "r"(dst), "l"(src), "r"(sz) : "memory");
}
#define CP_COMMIT() asm volatile("cp.async.commit_group;" ::: "memory")
#define CP_WAIT0()  asm volatile("cp.async.wait_group 0;" ::: "memory")
#define CP_WAIT1()  asm volatile("cp.async.wait_group 1;" ::: "memory")

// ---------------- zero: out + hist ----------------
__global__ void zero_all(float4* __restrict__ out, int n4)
{
    int i = blockIdx.x * blockDim.x + threadIdx.x;
    if (i < n4) out[i] = make_float4(0.f, 0.f, 0.f, 0.f);
    if (blockIdx.x == 0) {
        int* h = (int*)g_hist;
        for (int k = threadIdx.x; k < NCHUNK*NE; k += blockDim.x) h[k] = 0;
    }
}

// ---------------- fused routing + x-convert + hist  AND  weight transpose ----------------
#define RT_ROUTE_BLKS (NTOK/8)                 // 4096
#define RT_TRANS_BLKS (48*12*2*NE)             // 9216
__global__ void route_trans_kernel(const float* __restrict__ x,
                                   const float* __restrict__ noise,
                                   const float* __restrict__ wr, const float* __restrict__ br,
                                   const float* __restrict__ wn, const float* __restrict__ bn,
                                   const float* __restrict__ w1, const float* __restrict__ w2)
{
    int tid = threadIdx.x;
    if (blockIdx.x < RT_ROUTE_BLKS) {
        int warp = (blockIdx.x * blockDim.x + tid) >> 5;
        int lane = tid & 31;
        const float* xr = x + (size_t)warp * NC;
        float accr[NE], accn[NE];
#pragma unroll
        for (int e = 0; e < NE; e++) { accr[e] = 0.f; accn[e] = 0.f; }
        for (int c = lane; c < NC; c += 32) {
            float xv = xr[c];
            g_xh[(size_t)warp*NC + c] = __float2half_rn(xv);
#pragma unroll
            for (int e = 0; e < NE; e++) {
                accr[e] += xv * wr[c*NE + e];
                accn[e] += xv * wn[c*NE + e];
            }
        }
#pragma unroll
        for (int e = 0; e < NE; e++) {
#pragma unroll
            for (int o = 16; o > 0; o >>= 1) {
                accr[e] += __shfl_xor_sync(0xffffffffu, accr[e], o);
                accn[e] += __shfl_xor_sync(0xffffffffu, accn[e], o);
            }
        }
        if (lane == 0) {
            float v1 = -INFINITY, v2 = -INFINITY;
            int i1 = 0;
#pragma unroll
            for (int e = 0; e < NE; e++) {
                float z  = accn[e] + bn[e];
                float sp = (z > 20.f) ? z : log1pf(expf(z));
                float nv = accr[e] + br[e] + noise[(size_t)warp*NE + e] * sp;
                if (nv > v1) { v2 = v1; v1 = nv; i1 = e; }
                else if (nv > v2) { v2 = nv; }
            }
            g_expert[warp] = i1;
            g_gate[warp]   = 1.f / (1.f + expf(v2 - v1));
            atomicAdd(&g_hist[warp >> 7][i1], 1);
        }
    } else {
        __shared__ float t[32][33];
        int f = blockIdx.x - RT_ROUTE_BLKS;
        int xk = f % 48, yk = (f / 48) % 12, z = f / (48*12);
        int tx = tid & 31, ty = tid >> 5;
        int R, C, c_blk, r_blk;
        const float* s;
        __half* dh;
        if (z < NE) {
            R = NC; C = NDFF;
            s = w1 + (size_t)z * R * C;
            dh = g_w1h + (size_t)z * R * C;
            c_blk = xk; r_blk = yk;
        } else {
            R = NDFF; C = NC;
            s = w2 + (size_t)(z - NE) * R * C;
            dh = g_w2h + (size_t)(z - NE) * R * C;
            r_blk = xk; c_blk = yk;
        }
        int c0 = c_blk * 32, r0 = r_blk * 32;
#pragma unroll
        for (int i = 0; i < 32; i += 8)
            t[ty + i][tx] = s[(size_t)(r0 + ty + i) * C + c0 + tx];
        __syncthreads();
#pragma unroll
        for (int i = 0; i < 32; i += 8) {
            float v = t[tx][ty + i];
            dh[(size_t)(c0 + ty + i) * R + r0 + tx] = __float2half_rn(v);
        }
    }
}

// ---------------- dispatch ----------------
__global__ void scan_kernel()
{
    int e = threadIdx.x;
    if (e >= NE) return;
    int running = 0;
    for (int ch = 0; ch < NCHUNK; ch++) {
        g_base[ch][e] = running;
        running += g_hist[ch][e];
    }
    g_total[e] = running < CAP ? running : CAP;
}
__global__ void scatter_kernel()
{
    __shared__ int se[CHUNK];
    int tid = threadIdx.x;
    int t = blockIdx.x * CHUNK + tid;
    se[tid] = g_expert[t];
    __syncthreads();
    int e = se[tid];
    int rank = 0;
    for (int j = 0; j < tid; j++) rank += (se[j] == e);
    int pos = g_base[blockIdx.x][e] + rank;
    if (pos < CAP) {
        g_idx[e*CAP + pos]   = t;
        g_gslot[e*CAP + pos] = g_gate[t];
    }
}

#define TSTRIDE 40

// ================= GEMM1: B-panel-resident persistent CTAs =================
// Grid (4, 6, 8): m-chunk (16 m-tiles of 128), n-tile (256 wide), expert.
// B panel: 256 rows x 392 halves (K=384 + pad8). A streamed per m-tile,
// prefetch-distance-1 double buffer (load kt+1 overlaps compute kt; trailing
// barrier protects buffer reuse).
#define G1_BSTRIDE_H 392
#define G1_B_BYTES (256*G1_BSTRIDE_H*2)          // 200704
#define G1_ASTG    (128*TSTRIDE*2)               // 10240
#define G1_DYN     (G1_B_BYTES + 2*G1_ASTG)      // 221184

__global__ __launch_bounds__(256, 1)
void ffn1_mma(const float* __restrict__ b1)
{
    int e = blockIdx.z;
    int rows = g_total[e];
    int row_base = blockIdx.x * 2048;
    if (row_base >= rows) return;
    int n0 = blockIdx.y * 256;

    extern __shared__ char dyn[];
    uint32_t sB = smem_to_u32(dyn);
    uint32_t sA = sB + G1_B_BYTES;
    __shared__ int stok[128];

    int tid = threadIdx.x, lane = tid & 31, wid = tid >> 5;
    int wm = wid >> 2, wn = wid & 3;          // 2M x 4N warps, warp = 64x64

    // load B panel once: 256 rows x 48 chunks of 16B
    const __half* w1e = g_w1h + (size_t)e * NDFF * NC;
    for (int c = tid; c < 256*48; c += 256) {
        int row = c / 48, seg = c % 48;
        cp16(sB + (uint32_t)(row * G1_BSTRIDE_H + seg * 8) * 2,
             w1e + ((size_t)(n0 + row) * NC + seg * 8), 16);
    }
    CP_COMMIT();

    const float* b1e = b1 + (size_t)e * NDFF + n0;
    int r_in = lane >> 2, cpair = (lane & 3) * 2;
    uint32_t nloc = ((lane >> 4) & 1) * 8 + (lane & 7);

    for (int mt = 0; mt < 16; mt++) {
        int row0 = row_base + mt * 128;
        if (row0 >= rows) break;
        __syncthreads();
        if (tid < 128) {
            int r = row0 + tid;
            stok[tid] = (r < rows) ? g_idx[e*CAP + r] : -1;
        }
        __syncthreads();

        auto load_stageA = [&](int kt, int buf) {
            int k0 = kt * 32;
#pragma unroll
            for (int i = 0; i < 2; i++) {
                int c = tid + i * 256;
                int row = c >> 2, seg = c & 3;
                int tok = stok[row];
                const __half* src = g_xh + ((size_t)(tok < 0 ? 0 : tok) * NC + k0 + seg * 8);
                cp16(sA + buf * G1_ASTG + (uint32_t)(row * TSTRIDE + seg * 8) * 2,
                     src, (tok < 0) ? 0 : 16);
            }
            CP_COMMIT();
        };

        float acc[4][8][4];
#pragma unroll
        for (int i = 0; i < 4; i++)
#pragma unroll
            for (int j = 0; j < 8; j++)
#pragma unroll
                for (int q = 0; q < 4; q++) acc[i][j][q] = 0.f;

        const int NK = 12;
        load_stageA(0, 0);
        for (int kt = 0; kt < NK; kt++) {
            CP_WAIT0();
            __syncthreads();
            if (kt + 1 < NK) load_stageA(kt + 1, (kt + 1) & 1);
            uint32_t aBase = sA + (kt & 1) * G1_ASTG;
            int k0 = kt * 32;
#pragma unroll
            for (int ks = 0; ks < 32; ks += 16) {
                uint32_t bh[8][2];
                uint32_t kof = (uint32_t)(k0 + ks + ((lane >> 3) & 1) * 8);
#pragma unroll
                for (int jj = 0; jj < 4; jj++) {
                    uint32_t nr = (uint32_t)(wn * 64 + jj * 16) + nloc;
                    uint32_t r[4];
                    ldsm4(r, sB + (nr * G1_BSTRIDE_H + kof) * 2);
                    bh[jj*2][0]=r[0]; bh[jj*2][1]=r[1];
                    bh[jj*2+1][0]=r[2]; bh[jj*2+1][1]=r[3];
                }
                uint32_t arow = (uint32_t)(wm * 64 + (lane & 15));
                uint32_t acol = (uint32_t)(ks + (lane >> 4) * 8);
#pragma unroll
                for (int i = 0; i < 4; i++) {
                    uint32_t ah[4];
                    ldsm4(ah, aBase + ((arow + i * 16) * TSTRIDE + acol) * 2);
#pragma unroll
                    for (int j = 0; j < 8; j++)
                        mma16816(acc[i][j], ah, bh[j]);
                }
            }
            __syncthreads();
        }

        // epilogue: +bias, relu^2 -> fp16 H
#pragma unroll
        for (int i = 0; i < 4; i++) {
            int r = row0 + wm * 64 + i * 16 + r_in;
#pragma unroll
            for (int j = 0; j < 8; j++) {
                int col = wn * 64 + j * 8 + cpair;
                float bb0 = b1e[col], bb1 = b1e[col + 1];
                float v00 = fmaxf(acc[i][j][0] + bb0, 0.f); v00 *= v00;
                float v01 = fmaxf(acc[i][j][1] + bb1, 0.f); v01 *= v01;
                float v10 = fmaxf(acc[i][j][2] + bb0, 0.f); v10 *= v10;
                float v11 = fmaxf(acc[i][j][3] + bb1, 0.f); v11 *= v11;
                size_t o0 = ((size_t)e*CAP + r) * NDFF + n0 + col;
                size_t o1 = o0 + (size_t)8 * NDFF;
                __half2 p0; p0.x = __float2half_rn(v00); p0.y = __float2half_rn(v01);
                __half2 p1; p1.x = __float2half_rn(v10); p1.y = __float2half_rn(v11);
                *(__half2*)(g_Hh + o0) = p0;
                *(__half2*)(g_Hh + o1) = p1;
            }
        }
    }
}

// ================= GEMM2: 256x128 tile, 3-stage stream =================
// 8 warps as 4M x 2N, warp = 64x64. A = H (256 rows), B = w2T (128 rows).
// Prefetch distance 2 over a 3-buffer ring: (kt+2)%3 != kt%3, and the
// barrier at iteration start orders reuse of buffer (kt+2)%3 (last read kt-1).
#define G2_A_B   (256*TSTRIDE*2)                 // 20480
#define G2_B_B   (128*TSTRIDE*2)                 // 10240
#define G2_STAGE (G2_A_B + G2_B_B)               // 30720
#define G2_NSTG  3
#define G2_DYN   (G2_NSTG*G2_STAGE)              // 92160

__global__ __launch_bounds__(256, 1)
void ffn2_mma(const float* __restrict__ b2, float* __restrict__ out)
{
    int e = blockIdx.z;
    int rows = g_total[e];
    int row0 = blockIdx.x * 256;
    if (row0 >= rows) return;
    int n0 = blockIdx.y * 128;

    extern __shared__ char dyn[];
    uint32_t sbase = smem_to_u32(dyn);
    __shared__ int   stok[256];
    __shared__ float sg[256];

    int tid = threadIdx.x, lane = tid & 31, wid = tid >> 5;
    int wm = wid >> 1, wn = wid & 1;          // 4M x 2N warps, warp = 64x64
    {
        int r = row0 + tid;
        stok[tid] = (r < rows) ? g_idx[e*CAP + r] : -1;
        sg[tid]   = (r < rows) ? g_gslot[e*CAP + r] : 0.f;
    }
    __syncthreads();

    const __half* w2e = g_w2h + (size_t)e * NC * NDFF;
    const __half* hG  = g_Hh + (size_t)e * CAP * NDFF;

    auto load_stage = [&](int kt, int buf) {
        int k0 = kt * 32;
        uint32_t sb = sbase + buf * G2_STAGE;
#pragma unroll
        for (int i = 0; i < 6; i++) {
            int c = tid + i * 256;
            if (c < 1024) {
                int row = c >> 2, seg = c & 3;
                cp16(sb + (uint32_t)(row * TSTRIDE + seg * 8) * 2,
                     hG + ((size_t)(row0 + row) * NDFF + k0 + seg * 8), 16);
            } else {
                int t = c - 1024, row = t >> 2, seg = t & 3;
                cp16(sb + G2_A_B + (uint32_t)(row * TSTRIDE + seg * 8) * 2,
                     w2e + ((size_t)(n0 + row) * NDFF + k0 + seg * 8), 16);
            }
        }
        CP_COMMIT();
    };

    float acc[4][8][4];
#pragma unroll
    for (int i = 0; i < 4; i++)
#pragma unroll
        for (int j = 0; j < 8; j++)
#pragma unroll
            for (int q = 0; q < 4; q++) acc[i][j][q] = 0.f;

    uint32_t nloc = ((lane >> 4) & 1) * 8 + (lane & 7);
    const int NK = 48;
    load_stage(0, 0);
    load_stage(1, 1);
    for (int kt = 0; kt < NK; kt++) {
        if (kt + 1 == NK) { CP_WAIT0(); } else { CP_WAIT1(); }
        __syncthreads();
        if (kt + 2 < NK) load_stage(kt + 2, (kt + 2) % G2_NSTG);
        uint32_t aBase = sbase + (kt % G2_NSTG) * G2_STAGE;
        uint32_t bBase = aBase + G2_A_B;
#pragma unroll
        for (int ks = 0; ks < 32; ks += 16) {
            uint32_t bh[8][2];
            uint32_t kof = (uint32_t)(ks + ((lane >> 3) & 1) * 8);
#pragma unroll
            for (int jj = 0; jj < 4; jj++) {
                uint32_t nr = (uint32_t)(wn * 64 + jj * 16) + nloc;
                uint32_t r[4];
                ldsm4(r, bBase + (nr * TSTRIDE + kof) * 2);
                bh[jj*2][0]=r[0]; bh[jj*2][1]=r[1];
                bh[jj*2+1][0]=r[2]; bh[jj*2+1][1]=r[3];
            }
            uint32_t arow = (uint32_t)(wm * 64 + (lane & 15));
            uint32_t acol = (uint32_t)(ks + (lane >> 4) * 8);
#pragma unroll
            for (int i = 0; i < 4; i++) {
                uint32_t ah[4];
                ldsm4(ah, aBase + ((arow + i * 16) * TSTRIDE + acol) * 2);
#pragma unroll
                for (int j = 0; j < 8; j++)
                    mma16816(acc[i][j], ah, bh[j]);
            }
        }
    }

    // epilogue: (acc + b2) * gate, scattered float2 stores
    const float* b2e = b2 + (size_t)e * NC + n0;
    int r_in = lane >> 2, cpair = (lane & 3) * 2;
#pragma unroll
    for (int i = 0; i < 4; i++) {
        int rl0 = wm * 64 + i * 16 + r_in;
        int rl1 = rl0 + 8;
#pragma unroll
        for (int j = 0; j < 8; j++) {
            int col = wn * 64 + j * 8 + cpair;
            float bb0 = b2e[col], bb1 = b2e[col + 1];
            if (row0 + rl0 < rows) {
                int tok = stok[rl0]; float g = sg[rl0];
                float2 v = make_float2((acc[i][j][0] + bb0) * g, (acc[i][j][1] + bb1) * g);
                *(float2*)(out + (size_t)tok * NC + n0 + col) = v;
            }
            if (row0 + rl1 < rows) {
                int tok = stok[rl1]; float g = sg[rl1];
                float2 v = make_float2((acc[i][j][2] + bb0) * g, (acc[i][j][3] + bb1) * g);
                *(float2*)(out + (size_t)tok * NC + n0 + col) = v;
            }
        }
    }
}

// ---------------- launch ----------------
extern "C" void kernel_launch(void* const* d_in, const int* in_sizes, int n_in,
                              void* d_out, int out_size)
{
    const float* x  = (const float*)d_in[0];
    const float* noise = (const float*)d_in[1];
    const float* wr = (const float*)d_in[2];
    const float* br = (const float*)d_in[3];
    const float* wn = (const float*)d_in[4];
    const float* bn = (const float*)d_in[5];
    const float* w1 = (const float*)d_in[6];
    const float* b1 = (const float*)d_in[7];
    const float* w2 = (const float*)d_in[8];
    const float* b2 = (const float*)d_in[9];
    float* out = (float*)d_out;

    cudaFuncSetAttribute(ffn1_mma, cudaFuncAttributeMaxDynamicSharedMemorySize, G1_DYN);
    cudaFuncSetAttribute(ffn2_mma, cudaFuncAttributeMaxDynamicSharedMemorySize, G2_DYN);

    // 1: zero output + histogram
    int n4 = out_size / 4;
    zero_all<<<(n4 + 255)/256, 256>>>((float4*)out, n4);

    // 2: fused routing (+x cvt, +hist) and weight transpose+convert
    route_trans_kernel<<<RT_ROUTE_BLKS + RT_TRANS_BLKS, 256>>>(
        x, noise, wr, br, wn, bn, w1, w2);

    // 3-4: scan + stable scatter
    scan_kernel<<<1, 32>>>();
    scatter_kernel<<<NCHUNK, CHUNK>>>();

    // 5: GEMM1 (B-panel resident)
    dim3 g1(4, NDFF/256, NE);
    ffn1_mma<<<g1, 256, G1_DYN>>>(b1);

    // 6: GEMM2 (256x128)
    dim3 g2(CAP/256, NC/128, NE);
    ffn2_mma<<<g2, 256, G2_DYN>>>(b2, out);
}

// round 13
// speedup vs baseline: 1.0429x; 1.0429x over previous
#include <cuda_runtime.h>
#include <cuda_fp16.h>
#include <math.h>
#include <stdint.h>

// R12: identical to R11 (infra failure retry — no code change).

// Problem constants
#define NB 16
#define NT 2048
#define NC 384
#define NE 8
#define NDFF 1536
#define NTOK (NB*NT)          // 32768
#define CAP 8192
#define CHUNK 128
#define NCHUNK (NTOK/CHUNK)   // 256

// ---------------- device scratch ----------------
__device__ int   g_expert[NTOK];
__device__ float g_gate[NTOK];
__device__ int   g_hist[NCHUNK][NE];
__device__ int   g_base[NCHUNK][NE];
__device__ int   g_total[NE];
__device__ int   g_idx[NE*CAP];
__device__ float g_gslot[NE*CAP];

__device__ __half g_xh[(size_t)NTOK*NC];
__device__ __half g_w1h[(size_t)NE*NDFF*NC];   // [E][DFF][C] K-major
__device__ __half g_w2h[(size_t)NE*NC*NDFF];   // [E][C][DFF] K-major
__device__ __half g_Hh[(size_t)NE*CAP*NDFF];

// ---------------- helpers ----------------
__device__ __forceinline__ uint32_t smem_to_u32(const void* p) {
    uint32_t a;
    asm("{ .reg .u64 t; cvta.to.shared.u64 t, %1; cvt.u32.u64 %0, t; }" : "=r"(a) : "l"(p));
    return a;
}
__device__ __forceinline__ void ldsm4(uint32_t* r, uint32_t addr) {
    asm volatile("ldmatrix.sync.aligned.m8n8.x4.shared.b16 {%0,%1,%2,%3}, [%4];"
        : "=r"(r[0]), "=r"(r[1]), "=r"(r[2]), "=r"(r[3]) : "r"(addr));
}
__device__ __forceinline__ void mma16816(float* d, const uint32_t* a, const uint32_t* b) {
    asm volatile("mma.sync.aligned.m16n8k16.row.col.f32.f16.f16.f32 "
        "{%0,%1,%2,%3}, {%4,%5,%6,%7}, {%8,%9}, {%0,%1,%2,%3};"
        : "+f"(d[0]), "+f"(d[1]), "+f"(d[2]), "+f"(d[3])
        : "r"(a[0]), "r"(a[1]), "r"(a[2]), "r"(a[3]), "r"(b[0]), "r"(b[1]));
}
__device__ __forceinline__ void cp16(uint32_t dst, const void* src, int sz) {
    asm volatile("cp.async.cg.shared.global [%0], [%1], 16, %2;"
        :: "r"(dst), "l"(src), "r"(sz) : "memory");
}
#define CP_COMMIT() asm volatile("cp.async.commit_group;" ::: "memory")
#define CP_WAIT0()  asm volatile("cp.async.wait_group 0;" ::: "memory")
#define CP_WAIT1()  asm volatile("cp.async.wait_group 1;" ::: "memory")

// ---------------- zero: out + hist ----------------
__global__ void zero_all(float4* __restrict__ out, int n4)
{
    int i = blockIdx.x * blockDim.x + threadIdx.x;
    if (i < n4) out[i] = make_float4(0.f, 0.f, 0.f, 0.f);
    if (blockIdx.x == 0) {
        int* h = (int*)g_hist;
        for (int k = threadIdx.x; k < NCHUNK*NE; k += blockDim.x) h[k] = 0;
    }
}

// ---------------- fused routing + x-convert + hist  AND  weight transpose ----------------
#define RT_ROUTE_BLKS (NTOK/8)                 // 4096
#define RT_TRANS_BLKS (48*12*2*NE)             // 9216
__global__ void route_trans_kernel(const float* __restrict__ x,
                                   const float* __restrict__ noise,
                                   const float* __restrict__ wr, const float* __restrict__ br,
                                   const float* __restrict__ wn, const float* __restrict__ bn,
                                   const float* __restrict__ w1, const float* __restrict__ w2)
{
    int tid = threadIdx.x;
    if (blockIdx.x < RT_ROUTE_BLKS) {
        int warp = (blockIdx.x * blockDim.x + tid) >> 5;
        int lane = tid & 31;
        const float* xr = x + (size_t)warp * NC;
        float accr[NE], accn[NE];
#pragma unroll
        for (int e = 0; e < NE; e++) { accr[e] = 0.f; accn[e] = 0.f; }
        for (int c = lane; c < NC; c += 32) {
            float xv = xr[c];
            g_xh[(size_t)warp*NC + c] = __float2half_rn(xv);
#pragma unroll
            for (int e = 0; e < NE; e++) {
                accr[e] += xv * wr[c*NE + e];
                accn[e] += xv * wn[c*NE + e];
            }
        }
#pragma unroll
        for (int e = 0; e < NE; e++) {
#pragma unroll
            for (int o = 16; o > 0; o >>= 1) {
                accr[e] += __shfl_xor_sync(0xffffffffu, accr[e], o);
                accn[e] += __shfl_xor_sync(0xffffffffu, accn[e], o);
            }
        }
        if (lane == 0) {
            float v1 = -INFINITY, v2 = -INFINITY;
            int i1 = 0;
#pragma unroll
            for (int e = 0; e < NE; e++) {
                float z  = accn[e] + bn[e];
                float sp = (z > 20.f) ? z : log1pf(expf(z));
                float nv = accr[e] + br[e] + noise[(size_t)warp*NE + e] * sp;
                if (nv > v1) { v2 = v1; v1 = nv; i1 = e; }
                else if (nv > v2) { v2 = nv; }
            }
            g_expert[warp] = i1;
            g_gate[warp]   = 1.f / (1.f + expf(v2 - v1));
            atomicAdd(&g_hist[warp >> 7][i1], 1);
        }
    } else {
        __shared__ float t[32][33];
        int f = blockIdx.x - RT_ROUTE_BLKS;
        int xk = f % 48, yk = (f / 48) % 12, z = f / (48*12);
        int tx = tid & 31, ty = tid >> 5;
        int R, C, c_blk, r_blk;
        const float* s;
        __half* dh;
        if (z < NE) {
            R = NC; C = NDFF;
            s = w1 + (size_t)z * R * C;
            dh = g_w1h + (size_t)z * R * C;
            c_blk = xk; r_blk = yk;
        } else {
            R = NDFF; C = NC;
            s = w2 + (size_t)(z - NE) * R * C;
            dh = g_w2h + (size_t)(z - NE) * R * C;
            r_blk = xk; c_blk = yk;
        }
        int c0 = c_blk * 32, r0 = r_blk * 32;
#pragma unroll
        for (int i = 0; i < 32; i += 8)
            t[ty + i][tx] = s[(size_t)(r0 + ty + i) * C + c0 + tx];
        __syncthreads();
#pragma unroll
        for (int i = 0; i < 32; i += 8) {
            float v = t[tx][ty + i];
            dh[(size_t)(c0 + ty + i) * R + r0 + tx] = __float2half_rn(v);
        }
    }
}

// ---------------- dispatch ----------------
__global__ void scan_kernel()
{
    int e = threadIdx.x;
    if (e >= NE) return;
    int running = 0;
    for (int ch = 0; ch < NCHUNK; ch++) {
        g_base[ch][e] = running;
        running += g_hist[ch][e];
    }
    g_total[e] = running < CAP ? running : CAP;
}
__global__ void scatter_kernel()
{
    __shared__ int se[CHUNK];
    int tid = threadIdx.x;
    int t = blockIdx.x * CHUNK + tid;
    se[tid] = g_expert[t];
    __syncthreads();
    int e = se[tid];
    int rank = 0;
    for (int j = 0; j < tid; j++) rank += (se[j] == e);
    int pos = g_base[blockIdx.x][e] + rank;
    if (pos < CAP) {
        g_idx[e*CAP + pos]   = t;
        g_gslot[e*CAP + pos] = g_gate[t];
    }
}

#define TSTRIDE 40
#define TILE_B  10240

// ================= GEMM1: B-panel-resident, 256-row chunks =================
// Grid (32, 12, 8): 256-row chunk (2 m-tiles of 128), 128-wide n-tile, expert.
// B panel: 128 rows x 392 halves (K=384 + pad8) resident in smem (100 KB).
// A streamed per m-tile, proven dist-1 double buffer. Warp = 64x32 (2M x 4N).
#define G1_BSTRIDE_H 392
#define G1_B_BYTES (128*G1_BSTRIDE_H*2)          // 100352
#define G1_ASTG    (128*TSTRIDE*2)               // 10240
#define G1_DYN     (G1_B_BYTES + 2*G1_ASTG)      // 121088

__global__ __launch_bounds__(256, 1)
void ffn1_mma(const float* __restrict__ b1)
{
    int e = blockIdx.z;
    int rows = g_total[e];
    int row_base = blockIdx.x * 256;
    if (row_base >= rows) return;
    int n0 = blockIdx.y * 128;

    extern __shared__ char dyn[];
    uint32_t sB = smem_to_u32(dyn);
    uint32_t sA = sB + G1_B_BYTES;
    __shared__ int stok[128];

    int tid = threadIdx.x, lane = tid & 31, wid = tid >> 5;
    int wm = wid >> 2, wn = wid & 3;          // 2M x 4N warps, warp = 64x32

    // load B panel once: 128 rows x 48 chunks of 16B
    const __half* w1e = g_w1h + (size_t)e * NDFF * NC;
#pragma unroll
    for (int i = 0; i < 24; i++) {
        int c = tid + i * 256;
        int row = c / 48, seg = c % 48;
        cp16(sB + (uint32_t)(row * G1_BSTRIDE_H + seg * 8) * 2,
             w1e + ((size_t)(n0 + row) * NC + seg * 8), 16);
    }
    CP_COMMIT();

    const float* b1e = b1 + (size_t)e * NDFF + n0;
    int r_in = lane >> 2, cpair = (lane & 3) * 2;
    uint32_t nloc = ((lane >> 4) & 1) * 8 + (lane & 7);

    for (int mt = 0; mt < 2; mt++) {
        int row0 = row_base + mt * 128;
        if (row0 >= rows) break;
        __syncthreads();
        if (tid < 128) {
            int r = row0 + tid;
            stok[tid] = (r < rows) ? g_idx[e*CAP + r] : -1;
        }
        __syncthreads();

        auto load_stageA = [&](int kt, int buf) {
            int k0 = kt * 32;
#pragma unroll
            for (int i = 0; i < 2; i++) {
                int c = tid + i * 256;
                int row = c >> 2, seg = c & 3;
                int tok = stok[row];
                const __half* src = g_xh + ((size_t)(tok < 0 ? 0 : tok) * NC + k0 + seg * 8);
                cp16(sA + buf * G1_ASTG + (uint32_t)(row * TSTRIDE + seg * 8) * 2,
                     src, (tok < 0) ? 0 : 16);
            }
            CP_COMMIT();
        };

        float acc[4][4][4];
#pragma unroll
        for (int i = 0; i < 4; i++)
#pragma unroll
            for (int j = 0; j < 4; j++)
#pragma unroll
                for (int q = 0; q < 4; q++) acc[i][j][q] = 0.f;

        const int NK = 12;
        load_stageA(0, 0);
        for (int kt = 0; kt < NK; kt++) {
            CP_WAIT0();
            __syncthreads();
            if (kt + 1 < NK) load_stageA(kt + 1, (kt + 1) & 1);
            uint32_t aBase = sA + (kt & 1) * G1_ASTG;
            int k0 = kt * 32;
#pragma unroll
            for (int ks = 0; ks < 32; ks += 16) {
                uint32_t bh[4][2];
                uint32_t kof = (uint32_t)(k0 + ks + ((lane >> 3) & 1) * 8);
#pragma unroll
                for (int jj = 0; jj < 2; jj++) {
                    uint32_t nr = (uint32_t)(wn * 32 + jj * 16) + nloc;
                    uint32_t r[4];
                    ldsm4(r, sB + (nr * G1_BSTRIDE_H + kof) * 2);
                    bh[jj*2][0]=r[0]; bh[jj*2][1]=r[1];
                    bh[jj*2+1][0]=r[2]; bh[jj*2+1][1]=r[3];
                }
                uint32_t arow = (uint32_t)(wm * 64 + (lane & 15));
                uint32_t acol = (uint32_t)(ks + (lane >> 4) * 8);
#pragma unroll
                for (int i = 0; i < 4; i++) {
                    uint32_t ah[4];
                    ldsm4(ah, aBase + ((arow + i * 16) * TSTRIDE + acol) * 2);
#pragma unroll
                    for (int j = 0; j < 4; j++)
                        mma16816(acc[i][j], ah, bh[j]);
                }
            }
            __syncthreads();
        }

        // epilogue: +bias, relu^2 -> fp16 H
#pragma unroll
        for (int i = 0; i < 4; i++) {
            int r = row0 + wm * 64 + i * 16 + r_in;
#pragma unroll
            for (int j = 0; j < 4; j++) {
                int col = wn * 32 + j * 8 + cpair;
                float bb0 = b1e[col], bb1 = b1e[col + 1];
                float v00 = fmaxf(acc[i][j][0] + bb0, 0.f); v00 *= v00;
                float v01 = fmaxf(acc[i][j][1] + bb1, 0.f); v01 *= v01;
                float v10 = fmaxf(acc[i][j][2] + bb0, 0.f); v10 *= v10;
                float v11 = fmaxf(acc[i][j][3] + bb1, 0.f); v11 *= v11;
                size_t o0 = ((size_t)e*CAP + r) * NDFF + n0 + col;
                size_t o1 = o0 + (size_t)8 * NDFF;
                __half2 p0; p0.x = __float2half_rn(v00); p0.y = __float2half_rn(v01);
                __half2 p1; p1.x = __float2half_rn(v10); p1.y = __float2half_rn(v11);
                *(__half2*)(g_Hh + o0) = p0;
                *(__half2*)(g_Hh + o1) = p1;
            }
        }
    }
}

// ================= GEMM2: 128x128 tile, 3-stage stream (proven 549us version) =================
#define STAGE_B (2*TILE_B)       // 20480 (A + B)
#define NSTAGE  3
#define G2_DYN  (NSTAGE*STAGE_B) // 61440

__global__ __launch_bounds__(256, 2)
void ffn2_mma(const float* __restrict__ b2, float* __restrict__ out)
{
    int e = blockIdx.z;
    int rows = g_total[e];
    int row0 = blockIdx.x * 128;
    if (row0 >= rows) return;
    int n0 = blockIdx.y * 128;

    extern __shared__ char dyn[];
    uint32_t sbase = smem_to_u32(dyn);
    __shared__ int   stok[128];
    __shared__ float sg[128];

    int tid = threadIdx.x, lane = tid & 31, wid = tid >> 5;
    if (tid < 128) {
        int r = row0 + tid;
        stok[tid] = (r < rows) ? g_idx[e*CAP + r] : -1;
        sg[tid]   = (r < rows) ? g_gslot[e*CAP + r] : 0.f;
    }
    __syncthreads();

    const __half* w2e = g_w2h + (size_t)e * NC * NDFF;
    const __half* hG  = g_Hh + (size_t)e * CAP * NDFF;

    auto load_stage = [&](int kt, int buf) {
        int k0 = kt * 32;
        uint32_t sb = sbase + buf * STAGE_B;
#pragma unroll
        for (int i = 0; i < 4; i++) {
            int c = tid + i * 256;
            int arr = c >> 9, t = c & 511, row = t >> 2, seg = t & 3;
            uint32_t dst = sb + arr * TILE_B + (uint32_t)(row * TSTRIDE + seg * 8) * 2;
            if (arr == 0) {
                cp16(dst, hG + ((size_t)(row0 + row) * NDFF + k0 + seg * 8), 16);
            } else {
                cp16(dst, w2e + ((size_t)(n0 + row) * NDFF + k0 + seg * 8), 16);
            }
        }
        CP_COMMIT();
    };

    int wm = wid >> 2, wn = wid & 3;
    float acc[4][4][4];
#pragma unroll
    for (int i = 0; i < 4; i++)
#pragma unroll
        for (int j = 0; j < 4; j++)
#pragma unroll
            for (int q = 0; q < 4; q++) acc[i][j][q] = 0.f;

    auto compute_stage = [&](int buf) {
        uint32_t aBase = sbase + buf * STAGE_B;
        uint32_t bBase = aBase + TILE_B;
#pragma unroll
        for (int ks = 0; ks < 32; ks += 16) {
            uint32_t bh[4][2];
            uint32_t nloc = ((lane >> 4) & 1) * 8 + (lane & 7);
            uint32_t kof  = (uint32_t)(ks + ((lane >> 3) & 1) * 8);
#pragma unroll
            for (int jj = 0; jj < 2; jj++) {
                uint32_t bd = bBase + (((uint32_t)(wn * 32 + jj * 16) + nloc) * TSTRIDE + kof) * 2;
                uint32_t r[4];
                ldsm4(r, bd);
                bh[jj*2][0]=r[0]; bh[jj*2][1]=r[1]; bh[jj*2+1][0]=r[2]; bh[jj*2+1][1]=r[3];
            }
            uint32_t arow = (uint32_t)(wm * 64 + (lane & 15));
            uint32_t acol = (uint32_t)(ks + (lane >> 4) * 8);
#pragma unroll
            for (int i = 0; i < 4; i++) {
                uint32_t ah[4];
                ldsm4(ah, aBase + ((arow + i * 16) * TSTRIDE + acol) * 2);
#pragma unroll
                for (int j = 0; j < 4; j++)
                    mma16816(acc[i][j], ah, bh[j]);
            }
        }
    };

    const int NK = 48;
    load_stage(0, 0);
    load_stage(1, 1);
    for (int kt = 0; kt < NK; kt++) {
        if (kt + 1 == NK) { CP_WAIT0(); } else { CP_WAIT1(); }
        __syncthreads();
        if (kt + 2 < NK) load_stage(kt + 2, (kt + 2) % NSTAGE);
        compute_stage(kt % NSTAGE);
    }

    // epilogue: (acc + b2) * gate, scattered float2 stores
    const float* b2e = b2 + (size_t)e * NC + n0;
    int r_in = lane >> 2, cpair = (lane & 3) * 2;
#pragma unroll
    for (int i = 0; i < 4; i++) {
        int rl0 = wm * 64 + i * 16 + r_in;
        int rl1 = rl0 + 8;
#pragma unroll
        for (int j = 0; j < 4; j++) {
            int col = wn * 32 + j * 8 + cpair;
            float bb0 = b2e[col], bb1 = b2e[col + 1];
            if (row0 + rl0 < rows) {
                int tok = stok[rl0]; float g = sg[rl0];
                float2 v = make_float2((acc[i][j][0] + bb0) * g, (acc[i][j][1] + bb1) * g);
                *(float2*)(out + (size_t)tok * NC + n0 + col) = v;
            }
            if (row0 + rl1 < rows) {
                int tok = stok[rl1]; float g = sg[rl1];
                float2 v = make_float2((acc[i][j][2] + bb0) * g, (acc[i][j][3] + bb1) * g);
                *(float2*)(out + (size_t)tok * NC + n0 + col) = v;
            }
        }
    }
}

// ---------------- launch ----------------
extern "C" void kernel_launch(void* const* d_in, const int* in_sizes, int n_in,
                              void* d_out, int out_size)
{
    const float* x  = (const float*)d_in[0];
    const float* noise = (const float*)d_in[1];
    const float* wr = (const float*)d_in[2];
    const float* br = (const float*)d_in[3];
    const float* wn = (const float*)d_in[4];
    const float* bn = (const float*)d_in[5];
    const float* w1 = (const float*)d_in[6];
    const float* b1 = (const float*)d_in[7];
    const float* w2 = (const float*)d_in[8];
    const float* b2 = (const float*)d_in[9];
    float* out = (float*)d_out;

    cudaFuncSetAttribute(ffn1_mma, cudaFuncAttributeMaxDynamicSharedMemorySize, G1_DYN);
    cudaFuncSetAttribute(ffn2_mma, cudaFuncAttributeMaxDynamicSharedMemorySize, G2_DYN);

    // 1: zero output + histogram
    int n4 = out_size / 4;
    zero_all<<<(n4 + 255)/256, 256>>>((float4*)out, n4);

    // 2: fused routing (+x cvt, +hist) and weight transpose+convert
    route_trans_kernel<<<RT_ROUTE_BLKS + RT_TRANS_BLKS, 256>>>(
        x, noise, wr, br, wn, bn, w1, w2);

    // 3-4: scan + stable scatter
    scan_kernel<<<1, 32>>>();
    scatter_kernel<<<NCHUNK, CHUNK>>>();

    // 5: GEMM1 (B-panel resident, 256-row chunks)
    dim3 g1(CAP/256, NDFF/128, NE);
    ffn1_mma<<<g1, 256, G1_DYN>>>(b1);

    // 6: GEMM2 (proven 128x128, 3-stage)
    dim3 g2(CAP/128, NC/128, NE);
    ffn2_mma<<<g2, 256, G2_DYN>>>(b2, out);
}

// round 16
// speedup vs baseline: 1.3901x; 1.3330x over previous
#include <cuda_runtime.h>
#include <cuda_fp16.h>
#include <math.h>
#include <stdint.h>

// Problem constants
#define NB 16
#define NT 2048
#define NC 384
#define NE 8
#define NDFF 1536
#define NTOK (NB*NT)          // 32768
#define CAP 8192
#define CHUNK 128
#define NCHUNK (NTOK/CHUNK)   // 256

// ---------------- device scratch ----------------
__device__ int   g_expert[NTOK];
__device__ float g_gate[NTOK];
__device__ int   g_hist[NCHUNK][NE];
__device__ int   g_base[NCHUNK][NE];
__device__ int   g_total[NE];
__device__ int   g_idx[NE*CAP];
__device__ float g_gslot[NE*CAP];

__device__ __half g_xh[(size_t)NTOK*NC];
__device__ __half g_w1h[(size_t)NE*NDFF*NC];   // [E][DFF][C] K-major
__device__ __half g_w2h[(size_t)NE*NC*NDFF];   // [E][C][DFF] K-major
__device__ __half g_Hh[(size_t)NE*CAP*NDFF];

// ---------------- helpers ----------------
__device__ __forceinline__ uint32_t smem_to_u32(const void* p) {
    uint32_t a;
    asm("{ .reg .u64 t; cvta.to.shared.u64 t, %1; cvt.u32.u64 %0, t; }" : "=r"(a) : "l"(p));
    return a;
}
__device__ __forceinline__ void ldsm4(uint32_t* r, uint32_t addr) {
    asm volatile("ldmatrix.sync.aligned.m8n8.x4.shared.b16 {%0,%1,%2,%3}, [%4];"
        : "=r"(r[0]), "=r"(r[1]), "=r"(r[2]), "=r"(r[3]) : "r"(addr));
}
__device__ __forceinline__ void mma16816(float* d, const uint32_t* a, const uint32_t* b) {
    asm volatile("mma.sync.aligned.m16n8k16.row.col.f32.f16.f16.f32 "
        "{%0,%1,%2,%3}, {%4,%5,%6,%7}, {%8,%9}, {%0,%1,%2,%3};"
        : "+f"(d[0]), "+f"(d[1]), "+f"(d[2]), "+f"(d[3])
        : "r"(a[0]), "r"(a[1]), "r"(a[2]), "r"(a[3]), "r"(b[0]), "r"(b[1]));
}
__device__ __forceinline__ void cp16(uint32_t dst, const void* src, int sz) {
    asm volatile("cp.async.cg.shared.global [%0], [%1], 16, %2;"
        :: "r"(dst), "l"(src), "r"(sz) : "memory");
}
#define CP_COMMIT() asm volatile("cp.async.commit_group;" ::: "memory")
#define CP_WAIT0()  asm volatile("cp.async.wait_group 0;" ::: "memory")
#define CP_WAIT1()  asm volatile("cp.async.wait_group 1;" ::: "memory")

// ---------------- zero: out + hist ----------------
__global__ void zero_all(float4* __restrict__ out, int n4)
{
    int i = blockIdx.x * blockDim.x + threadIdx.x;
    if (i < n4) out[i] = make_float4(0.f, 0.f, 0.f, 0.f);
    if (blockIdx.x == 0) {
        int* h = (int*)g_hist;
        for (int k = threadIdx.x; k < NCHUNK*NE; k += blockDim.x) h[k] = 0;
    }
}

// ---------------- fused routing + x-convert + hist  AND  weight transpose ----------------
#define RT_ROUTE_BLKS (NTOK/8)                 // 4096
#define RT_TRANS_BLKS (48*12*2*NE)             // 9216
__global__ void route_trans_kernel(const float* __restrict__ x,
                                   const float* __restrict__ noise,
                                   const float* __restrict__ wr, const float* __restrict__ br,
                                   const float* __restrict__ wn, const float* __restrict__ bn,
                                   const float* __restrict__ w1, const float* __restrict__ w2)
{
    int tid = threadIdx.x;
    if (blockIdx.x < RT_ROUTE_BLKS) {
        int warp = (blockIdx.x * blockDim.x + tid) >> 5;
        int lane = tid & 31;
        const float* xr = x + (size_t)warp * NC;
        float accr[NE], accn[NE];
#pragma unroll
        for (int e = 0; e < NE; e++) { accr[e] = 0.f; accn[e] = 0.f; }
        for (int c = lane; c < NC; c += 32) {
            float xv = xr[c];
            g_xh[(size_t)warp*NC + c] = __float2half_rn(xv);
#pragma unroll
            for (int e = 0; e < NE; e++) {
                accr[e] += xv * wr[c*NE + e];
                accn[e] += xv * wn[c*NE + e];
            }
        }
#pragma unroll
        for (int e = 0; e < NE; e++) {
#pragma unroll
            for (int o = 16; o > 0; o >>= 1) {
                accr[e] += __shfl_xor_sync(0xffffffffu, accr[e], o);
                accn[e] += __shfl_xor_sync(0xffffffffu, accn[e], o);
            }
        }
        if (lane == 0) {
            float v1 = -INFINITY, v2 = -INFINITY;
            int i1 = 0;
#pragma unroll
            for (int e = 0; e < NE; e++) {
                float z  = accn[e] + bn[e];
                float sp = (z > 20.f) ? z : log1pf(expf(z));
                float nv = accr[e] + br[e] + noise[(size_t)warp*NE + e] * sp;
                if (nv > v1) { v2 = v1; v1 = nv; i1 = e; }
                else if (nv > v2) { v2 = nv; }
            }
            g_expert[warp] = i1;
            g_gate[warp]   = 1.f / (1.f + expf(v2 - v1));
            atomicAdd(&g_hist[warp >> 7][i1], 1);
        }
    } else {
        __shared__ float t[32][33];
        int f = blockIdx.x - RT_ROUTE_BLKS;
        int xk = f % 48, yk = (f / 48) % 12, z = f / (48*12);
        int tx = tid & 31, ty = tid >> 5;
        int R, C, c_blk, r_blk;
        const float* s;
        __half* dh;
        if (z < NE) {
            R = NC; C = NDFF;
            s = w1 + (size_t)z * R * C;
            dh = g_w1h + (size_t)z * R * C;
            c_blk = xk; r_blk = yk;
        } else {
            R = NDFF; C = NC;
            s = w2 + (size_t)(z - NE) * R * C;
            dh = g_w2h + (size_t)(z - NE) * R * C;
            r_blk = xk; c_blk = yk;
        }
        int c0 = c_blk * 32, r0 = r_blk * 32;
#pragma unroll
        for (int i = 0; i < 32; i += 8)
            t[ty + i][tx] = s[(size_t)(r0 + ty + i) * C + c0 + tx];
        __syncthreads();
#pragma unroll
        for (int i = 0; i < 32; i += 8) {
            float v = t[tx][ty + i];
            dh[(size_t)(c0 + ty + i) * R + r0 + tx] = __float2half_rn(v);
        }
    }
}

// ---------------- dispatch ----------------
// warp-per-expert Kogge-Stone scan over chunk histograms
__global__ void scan_kernel()
{
    int wid = threadIdx.x >> 5, lane = threadIdx.x & 31;
    if (wid >= NE) return;
    int running = 0;
    for (int g = 0; g < NCHUNK; g += 32) {
        int v = g_hist[g + lane][wid];
        int s = v;
#pragma unroll
        for (int o = 1; o < 32; o <<= 1) {
            int t = __shfl_up_sync(0xffffffffu, s, o);
            if (lane >= o) s += t;
        }
        g_base[g + lane][wid] = running + s - v;     // exclusive
        running += __shfl_sync(0xffffffffu, s, 31);
    }
    if (lane == 0) g_total[wid] = running < CAP ? running : CAP;
}
__global__ void scatter_kernel()
{
    __shared__ int se[CHUNK];
    int tid = threadIdx.x;
    int t = blockIdx.x * CHUNK + tid;
    se[tid] = g_expert[t];
    __syncthreads();
    int e = se[tid];
    int rank = 0;
    for (int j = 0; j < tid; j++) rank += (se[j] == e);
    int pos = g_base[blockIdx.x][e] + rank;
    if (pos < CAP) {
        g_idx[e*CAP + pos]   = t;
        g_gslot[e*CAP + pos] = g_gate[t];
    }
}

// ================= fp16 mma FFN kernels =================
// Tile 128(M) x 128(N), K-tile 64, 8 warps (2M x 4N), warp = 64x32.
// Rows padded to 72 halves (144 B): ldsm row offsets mod 128 distinct -> conflict-free.
// 3-stage cp.async ring, prefetch distance 2, one __syncthreads per K-iter.
#define TSTRIDE  72
#define TILE_B   (128*TSTRIDE*2)     // 18432
#define STAGE_B  (2*TILE_B)          // 36864 (A + B)
#define NSTAGE   3
#define DYN_B    (NSTAGE*STAGE_B)    // 110592

// GEMM1: A = gathered x, B = w1T, K=384 (6 iters). Out -> H fp16 after bias/relu^2.
__global__ __launch_bounds__(256, 2)
void ffn1_mma(const float* __restrict__ b1)
{
    int e = blockIdx.z;
    int rows = g_total[e];
    int row0 = blockIdx.x * 128;
    if (row0 >= rows) return;
    int n0 = blockIdx.y * 128;

    extern __shared__ char dyn[];
    uint32_t sbase = smem_to_u32(dyn);
    __shared__ int stok[128];

    int tid = threadIdx.x, lane = tid & 31, wid = tid >> 5;
    if (tid < 128) {
        int r = row0 + tid;
        stok[tid] = (r < rows) ? g_idx[e*CAP + r] : -1;
    }
    __syncthreads();

    const __half* w1e = g_w1h + (size_t)e * NDFF * NC;

    // 2048 16B chunks per stage: arr(2) x row(128) x seg(8)
    auto load_stage = [&](int kt, int buf) {
        int k0 = kt * 64;
        uint32_t sb = sbase + buf * STAGE_B;
#pragma unroll
        for (int i = 0; i < 8; i++) {
            int c = tid + i * 256;
            int arr = c >> 10, t = c & 1023, row = t >> 3, seg = t & 7;
            uint32_t dst = sb + arr * TILE_B + (uint32_t)(row * TSTRIDE + seg * 8) * 2;
            if (arr == 0) {
                int tok = stok[row];
                const __half* src = g_xh + ((size_t)(tok < 0 ? 0 : tok) * NC + k0 + seg * 8);
                cp16(dst, src, (tok < 0) ? 0 : 16);
            } else {
                cp16(dst, w1e + ((size_t)(n0 + row) * NC + k0 + seg * 8), 16);
            }
        }
        CP_COMMIT();
    };

    int wm = wid >> 2, wn = wid & 3;
    float acc[4][4][4];
#pragma unroll
    for (int i = 0; i < 4; i++)
#pragma unroll
        for (int j = 0; j < 4; j++)
#pragma unroll
            for (int q = 0; q < 4; q++) acc[i][j][q] = 0.f;

    auto compute_stage = [&](int buf) {
        uint32_t aBase = sbase + buf * STAGE_B;
        uint32_t bBase = aBase + TILE_B;
#pragma unroll
        for (int ks = 0; ks < 64; ks += 16) {
            uint32_t bh[4][2];
            uint32_t nloc = ((lane >> 4) & 1) * 8 + (lane & 7);
            uint32_t kof  = (uint32_t)(ks + ((lane >> 3) & 1) * 8);
#pragma unroll
            for (int jj = 0; jj < 2; jj++) {
                uint32_t bd = bBase + (((uint32_t)(wn * 32 + jj * 16) + nloc) * TSTRIDE + kof) * 2;
                uint32_t r[4];
                ldsm4(r, bd);
                bh[jj*2][0]=r[0]; bh[jj*2][1]=r[1]; bh[jj*2+1][0]=r[2]; bh[jj*2+1][1]=r[3];
            }
            uint32_t arow = (uint32_t)(wm * 64 + (lane & 15));
            uint32_t acol = (uint32_t)(ks + (lane >> 4) * 8);
#pragma unroll
            for (int i = 0; i < 4; i++) {
                uint32_t ah[4];
                ldsm4(ah, aBase + ((arow + i * 16) * TSTRIDE + acol) * 2);
#pragma unroll
                for (int j = 0; j < 4; j++)
                    mma16816(acc[i][j], ah, bh[j]);
            }
        }
    };

    const int NK = 6;   // 384 / 64
    load_stage(0, 0);
    load_stage(1, 1);
    for (int kt = 0; kt < NK; kt++) {
        if (kt + 1 == NK) { CP_WAIT0(); } else { CP_WAIT1(); }
        __syncthreads();
        if (kt + 2 < NK) load_stage(kt + 2, (kt + 2) % NSTAGE);
        compute_stage(kt % NSTAGE);
    }

    // epilogue: +bias, relu^2 -> fp16 H
    const float* b1e = b1 + (size_t)e * NDFF + n0;
    int r_in = lane >> 2, cpair = (lane & 3) * 2;
#pragma unroll
    for (int i = 0; i < 4; i++) {
        int r = row0 + wm * 64 + i * 16 + r_in;
#pragma unroll
        for (int j = 0; j < 4; j++) {
            int col = wn * 32 + j * 8 + cpair;
            float bb0 = b1e[col], bb1 = b1e[col + 1];
            float v00 = fmaxf(acc[i][j][0] + bb0, 0.f); v00 *= v00;
            float v01 = fmaxf(acc[i][j][1] + bb1, 0.f); v01 *= v01;
            float v10 = fmaxf(acc[i][j][2] + bb0, 0.f); v10 *= v10;
            float v11 = fmaxf(acc[i][j][3] + bb1, 0.f); v11 *= v11;
            size_t o0 = ((size_t)e*CAP + r) * NDFF + n0 + col;
            size_t o1 = o0 + (size_t)8 * NDFF;
            __half2 p0; p0.x = __float2half_rn(v00); p0.y = __float2half_rn(v01);
            __half2 p1; p1.x = __float2half_rn(v10); p1.y = __float2half_rn(v11);
            *(__half2*)(g_Hh + o0) = p0;
            *(__half2*)(g_Hh + o1) = p1;
        }
    }
}

// GEMM2: A = H, B = w2T, K=1536 (24 iters). Out -> scatter (acc+b2)*gate.
__global__ __launch_bounds__(256, 2)
void ffn2_mma(const float* __restrict__ b2, float* __restrict__ out)
{
    int e = blockIdx.z;
    int rows = g_total[e];
    int row0 = blockIdx.x * 128;
    if (row0 >= rows) return;
    int n0 = blockIdx.y * 128;

    extern __shared__ char dyn[];
    uint32_t sbase = smem_to_u32(dyn);
    __shared__ int   stok[128];
    __shared__ float sg[128];

    int tid = threadIdx.x, lane = tid & 31, wid = tid >> 5;
    if (tid < 128) {
        int r = row0 + tid;
        stok[tid] = (r < rows) ? g_idx[e*CAP + r] : -1;
        sg[tid]   = (r < rows) ? g_gslot[e*CAP + r] : 0.f;
    }
    __syncthreads();

    const __half* w2e = g_w2h + (size_t)e * NC * NDFF;
    const __half* hG  = g_Hh + (size_t)e * CAP * NDFF;

    auto load_stage = [&](int kt, int buf) {
        int k0 = kt * 64;
        uint32_t sb = sbase + buf * STAGE_B;
#pragma unroll
        for (int i = 0; i < 8; i++) {
            int c = tid + i * 256;
            int arr = c >> 10, t = c & 1023, row = t >> 3, seg = t & 7;
            uint32_t dst = sb + arr * TILE_B + (uint32_t)(row * TSTRIDE + seg * 8) * 2;
            if (arr == 0) {
                cp16(dst, hG + ((size_t)(row0 + row) * NDFF + k0 + seg * 8), 16);
            } else {
                cp16(dst, w2e + ((size_t)(n0 + row) * NDFF + k0 + seg * 8), 16);
            }
        }
        CP_COMMIT();
    };

    int wm = wid >> 2, wn = wid & 3;
    float acc[4][4][4];
#pragma unroll
    for (int i = 0; i < 4; i++)
#pragma unroll
        for (int j = 0; j < 4; j++)
#pragma unroll
            for (int q = 0; q < 4; q++) acc[i][j][q] = 0.f;

    auto compute_stage = [&](int buf) {
        uint32_t aBase = sbase + buf * STAGE_B;
        uint32_t bBase = aBase + TILE_B;
#pragma unroll
        for (int ks = 0; ks < 64; ks += 16) {
            uint32_t bh[4][2];
            uint32_t nloc = ((lane >> 4) & 1) * 8 + (lane & 7);
            uint32_t kof  = (uint32_t)(ks + ((lane >> 3) & 1) * 8);
#pragma unroll
            for (int jj = 0; jj < 2; jj++) {
                uint32_t bd = bBase + (((uint32_t)(wn * 32 + jj * 16) + nloc) * TSTRIDE + kof) * 2;
                uint32_t r[4];
                ldsm4(r, bd);
                bh[jj*2][0]=r[0]; bh[jj*2][1]=r[1]; bh[jj*2+1][0]=r[2]; bh[jj*2+1][1]=r[3];
            }
            uint32_t arow = (uint32_t)(wm * 64 + (lane & 15));
            uint32_t acol = (uint32_t)(ks + (lane >> 4) * 8);
#pragma unroll
            for (int i = 0; i < 4; i++) {
                uint32_t ah[4];
                ldsm4(ah, aBase + ((arow + i * 16) * TSTRIDE + acol) * 2);
#pragma unroll
                for (int j = 0; j < 4; j++)
                    mma16816(acc[i][j], ah, bh[j]);
            }
        }
    };

    const int NK = 24;  // 1536 / 64
    load_stage(0, 0);
    load_stage(1, 1);
    for (int kt = 0; kt < NK; kt++) {
        if (kt + 1 == NK) { CP_WAIT0(); } else { CP_WAIT1(); }
        __syncthreads();
        if (kt + 2 < NK) load_stage(kt + 2, (kt + 2) % NSTAGE);
        compute_stage(kt % NSTAGE);
    }

    // epilogue: (acc + b2) * gate, scattered float2 stores
    const float* b2e = b2 + (size_t)e * NC + n0;
    int r_in = lane >> 2, cpair = (lane & 3) * 2;
#pragma unroll
    for (int i = 0; i < 4; i++) {
        int rl0 = wm * 64 + i * 16 + r_in;
        int rl1 = rl0 + 8;
#pragma unroll
        for (int j = 0; j < 4; j++) {
            int col = wn * 32 + j * 8 + cpair;
            float bb0 = b2e[col], bb1 = b2e[col + 1];
            if (row0 + rl0 < rows) {
                int tok = stok[rl0]; float g = sg[rl0];
                float2 v = make_float2((acc[i][j][0] + bb0) * g, (acc[i][j][1] + bb1) * g);
                *(float2*)(out + (size_t)tok * NC + n0 + col) = v;
            }
            if (row0 + rl1 < rows) {
                int tok = stok[rl1]; float g = sg[rl1];
                float2 v = make_float2((acc[i][j][2] + bb0) * g, (acc[i][j][3] + bb1) * g);
                *(float2*)(out + (size_t)tok * NC + n0 + col) = v;
            }
        }
    }
}

// ---------------- launch ----------------
extern "C" void kernel_launch(void* const* d_in, const int* in_sizes, int n_in,
                              void* d_out, int out_size)
{
    const float* x  = (const float*)d_in[0];
    const float* noise = (const float*)d_in[1];
    const float* wr = (const float*)d_in[2];
    const float* br = (const float*)d_in[3];
    const float* wn = (const float*)d_in[4];
    const float* bn = (const float*)d_in[5];
    const float* w1 = (const float*)d_in[6];
    const float* b1 = (const float*)d_in[7];
    const float* w2 = (const float*)d_in[8];
    const float* b2 = (const float*)d_in[9];
    float* out = (float*)d_out;

    cudaFuncSetAttribute(ffn1_mma, cudaFuncAttributeMaxDynamicSharedMemorySize, DYN_B);
    cudaFuncSetAttribute(ffn2_mma, cudaFuncAttributeMaxDynamicSharedMemorySize, DYN_B);

    // 1: zero output + histogram
    int n4 = out_size / 4;
    zero_all<<<(n4 + 255)/256, 256>>>((float4*)out, n4);

    // 2: fused routing (+x cvt, +hist) and weight transpose+convert
    route_trans_kernel<<<RT_ROUTE_BLKS + RT_TRANS_BLKS, 256>>>(
        x, noise, wr, br, wn, bn, w1, w2);

    // 3-4: parallel scan + stable scatter
    scan_kernel<<<1, 256>>>();
    scatter_kernel<<<NCHUNK, CHUNK>>>();

    // 5: GEMM1 (streaming 128x128, K-tile 64)
    dim3 g1(CAP/128, NDFF/128, NE);
    ffn1_mma<<<g1, 256, DYN_B>>>(b1);

    // 6: GEMM2 (streaming 128x128, K-tile 64)
    dim3 g2(CAP/128, NC/128, NE);
    ffn2_mma<<<g2, 256, DYN_B>>>(b2, out);
}